// round 3
// baseline (speedup 1.0000x reference)
#include <cuda_runtime.h>
#include <cstdint>

#define HW      262144
#define NB      8
#define NC      16
#define NBC     (NB * NC)          // 128 class-planes
#define KB      8192               // histogram buckets over error in (0,2)
#define THREADS 1024
#define BPT     (KB / THREADS)     // 8 buckets per thread

// Scratch (no allocations allowed): labels as uint8, per-block deterministic partials.
__device__ unsigned char g_labels[NB * HW];
__device__ double        g_part[NBC * 2];   // [bc*2]=lovasz, [bc*2+1]=bce
__device__ int           g_is32;            // 1 if target buffer is int32, 0 if int64

__device__ __forceinline__ float fast_ex2(float x) { float y; asm("ex2.approx.f32 %0, %1;" : "=f"(y) : "f"(x)); return y; }
__device__ __forceinline__ float fast_lg2(float x) { float y; asm("lg2.approx.f32 %0, %1;" : "=f"(y) : "f"(x)); return y; }
__device__ __forceinline__ float fast_rcp(float x) { float y; asm("rcp.approx.f32 %0, %1;" : "=f"(y) : "f"(x)); return y; }

// K-detect: decide whether target is int32 or int64.
// Reads only 8 KB (safe under either dtype). If int64, every high word is 0
// (labels are 0..16). If int32, "high words" are the following labels and the
// OR over 1024 of them is nonzero (prob 1 - (1/17)^1024).
__global__ void detect_kernel(const unsigned long long* __restrict__ t) {
    __shared__ unsigned s[256];
    unsigned hi = 0;
    for (int k = threadIdx.x; k < 1024; k += 256) hi |= (unsigned)(t[k] >> 32);
    s[threadIdx.x] = hi;
    __syncthreads();
    if (threadIdx.x == 0) {
        unsigned r = 0;
        for (int i = 0; i < 256; i++) r |= s[i];
        g_is32 = (r != 0) ? 1 : 0;
    }
}

// K0: target (int32 or int64) -> uint8 (values 0..16)
__global__ void prep_kernel(const void* __restrict__ target) {
    int i = blockIdx.x * blockDim.x + threadIdx.x;
    if (i < NB * HW) {
        unsigned char v;
        if (g_is32) v = (unsigned char)((const int*)target)[i];
        else        v = (unsigned char)((const long long*)target)[i];
        g_labels[i] = v;
    }
}

// K1: one block per (b,c). Histogram of quantized errors + fused BCE partial,
// then in-block suffix scan + exact-integer Jaccard integral.
__global__ __launch_bounds__(THREADS, 1) void lovasz_kernel(const float* __restrict__ logits) {
    __shared__ unsigned int       hist[KB];      // low16 = count, high16 = positive count
    __shared__ unsigned long long sbuf[THREADS]; // scan scratch: (n<<32)|p
    __shared__ double             wsum[32][2];

    const int bc  = blockIdx.x;
    const int b   = bc >> 4;
    const int c   = bc & 15;
    const int tid = threadIdx.x;

    for (int j = tid; j < KB; j += THREADS) hist[j] = 0u;
    __syncthreads();

    const float4* lg4 = reinterpret_cast<const float4*>(logits + (size_t)bc * HW);
    const uchar4* lb4 = reinterpret_cast<const uchar4*>(g_labels + (size_t)b * HW);

    float bce_acc = 0.0f;
    const float L2E = 1.4426950408889634f;
    const float LN2 = 0.6931471805599453f;

    for (int q = tid; q < HW / 4; q += THREADS) {
        float4 z4 = lg4[q];
        uchar4 t4 = lb4[q];
        float zz[4] = { z4.x, z4.y, z4.z, z4.w };
        int   tt[4] = { t4.x, t4.y, t4.z, t4.w };
        #pragma unroll
        for (int j = 0; j < 4; j++) {
            float z   = zz[j];
            int   t   = tt[j];
            int   lbl = (t == c) ? 1 : 0;   // t==16 (ignore) is never == c, so lbl=0 there
            float az  = fabsf(z);
            float u   = fast_ex2(-az * L2E);              // e^{-|z|}
            float u2  = u * u;                            // e^{-2|z|}
            float tnh = (1.0f - u2) * fast_rcp(1.0f + u2);// tanh(|z|), abs err ~2e-7
            float x   = (z < 0.0f) ? -tnh : tnh;          // tanh(z)
            float e   = lbl ? (1.0f - x) : (1.0f + x);    // hinge error in (0,2)
            e = fmaxf(e, 0.0f);
            int key = (int)(e * (float)(KB / 2));
            key = min(key, KB - 1);
            atomicAdd(&hist[key], 1u + ((unsigned)lbl << 16));
            // BCE (clip at 100 per reference; valid = t < NC)
            float m   = fast_lg2(1.0f + u) * LN2;         // log1p(e^{-|z|})
            float sp  = fmaxf(z, 0.0f) + m;               // softplus(z)
            float bce = fminf(sp - (lbl ? z : 0.0f), 100.0f);
            if (t < NC) bce_acc += bce;
        }
    }
    __syncthreads();

    // Per-thread bucket totals over its 8 consecutive buckets.
    unsigned int n_t = 0, p_t = 0;
    const int lo = tid * BPT;
    #pragma unroll
    for (int j = 0; j < BPT; j++) {
        unsigned v = hist[lo + j];
        n_t += v & 0xFFFFu;
        p_t += v >> 16;
    }
    sbuf[tid] = ((unsigned long long)n_t << 32) | (unsigned long long)p_t;
    __syncthreads();
    // Inclusive SUFFIX scan (descending-error order = descending bucket index).
    for (int d = 1; d < THREADS; d <<= 1) {
        unsigned long long v = (tid + d < THREADS) ? sbuf[tid + d] : 0ULL;
        __syncthreads();
        sbuf[tid] += v;
        __syncthreads();
    }
    const unsigned long long tot = sbuf[0];
    const long long P = (long long)(tot & 0xFFFFFFFFULL);   // total positives this class
    unsigned long long inc = sbuf[tid];
    long long i0 = (long long)(inc >> 32) - (long long)n_t; // elements strictly above my range
    long long p0 = (long long)(inc & 0xFFFFFFFFULL) - (long long)p_t;

    // Walk my buckets high->low; exact integer Jaccard deltas.
    double contrib = 0.0;
    const double de = 2.0 / (double)KB;
    for (int j = BPT - 1; j >= 0; j--) {
        unsigned v = hist[lo + j];
        long long n = (long long)(v & 0xFFFFu);
        long long p = (long long)(v >> 16);
        if (n > 0) {
            long long i1 = i0 + n, p1 = p0 + p;
            double dJ;
            if (P > 0) {
                long long A0 = P - p0, B0 = P + i0 - p0;
                long long A1 = P - p1, B1 = P + i1 - p1;
                dJ = (double)(A0 * B1 - A1 * B0) / ((double)B0 * (double)B1);
            } else {
                dJ = (i0 == 0) ? 1.0 : 0.0;  // degenerate: grad = [1,0,0,...]
            }
            double erep = ((double)(lo + j) + 0.5) * de;   // bucket-midpoint error
            contrib += erep * dJ;
            i0 = i1; p0 = p1;
        }
    }

    // Deterministic block reduction (shfl + fixed-order), write per-block slot.
    double bced = (double)bce_acc;
    const unsigned mask = 0xFFFFFFFFu;
    #pragma unroll
    for (int off = 16; off > 0; off >>= 1) {
        contrib += __shfl_down_sync(mask, contrib, off);
        bced    += __shfl_down_sync(mask, bced, off);
    }
    const int wid = tid >> 5, lane = tid & 31;
    if (lane == 0) { wsum[wid][0] = contrib; wsum[wid][1] = bced; }
    __syncthreads();
    if (wid == 0) {
        double cv = wsum[lane][0];
        double bv = wsum[lane][1];
        #pragma unroll
        for (int off = 16; off > 0; off >>= 1) {
            cv += __shfl_down_sync(mask, cv, off);
            bv += __shfl_down_sync(mask, bv, off);
        }
        if (lane == 0) { g_part[bc * 2 + 0] = cv; g_part[bc * 2 + 1] = bv; }
    }
}

// K2: deterministic final combine (fixed summation order).
__global__ void final_kernel(float* __restrict__ out) {
    double lov = 0.0, bce = 0.0;
    for (int i = 0; i < NBC; i++) { lov += g_part[i * 2]; bce += g_part[i * 2 + 1]; }
    out[0] = (float)(lov * (1.0 / 128.0) + bce * (1.0 / 33554432.0));
}

extern "C" void kernel_launch(void* const* d_in, const int* in_sizes, int n_in,
                              void* d_out, int out_size) {
    const float* logits;
    const void*  target;
    if (in_sizes[0] == NB * NC * HW) {
        logits = (const float*)d_in[0];
        target = d_in[1];
    } else {
        logits = (const float*)d_in[1];
        target = d_in[0];
    }
    detect_kernel<<<1, 256>>>((const unsigned long long*)target);
    prep_kernel<<<(NB * HW + 255) / 256, 256>>>(target);
    lovasz_kernel<<<NBC, THREADS>>>(logits);
    final_kernel<<<1, 1>>>((float*)d_out);
}

// round 4
// speedup vs baseline: 1.2000x; 1.2000x over previous
#include <cuda_runtime.h>
#include <cstdint>

#define HW      262144
#define NB      8
#define NC      16
#define NBC     (NB * NC)          // 128 class-planes
#define KB      8192               // histogram buckets over error in (0,2)
#define THREADS 1024
#define BPT     (KB / THREADS)     // 8 buckets per thread

// Scratch (no allocations allowed)
__device__ unsigned char g_labels[NB * HW];
__device__ double        g_part[NBC * 2];   // [bc*2]=lovasz, [bc*2+1]=bce
__device__ unsigned int  g_arrive;          // zero-initialized; reset by combiner each call

__device__ __forceinline__ float fast_ex2(float x) { float y; asm("ex2.approx.f32 %0, %1;" : "=f"(y) : "f"(x)); return y; }
__device__ __forceinline__ float fast_lg2(float x) { float y; asm("lg2.approx.f32 %0, %1;" : "=f"(y) : "f"(x)); return y; }
__device__ __forceinline__ float fast_rcp(float x) { float y; asm("rcp.approx.f32 %0, %1;" : "=f"(y) : "f"(x)); return y; }

// K0: target (int32 or int64) -> uint8. Dtype detected per-block (uniform branch):
// read first 64 values as int64; if really int64, all high words are 0 (labels 0..16);
// if int32, high words are following labels, OR != 0 with prob 1 - 17^-64.
__global__ __launch_bounds__(THREADS) void prep_kernel(const void* __restrict__ target) {
    __shared__ int s_is32;
    if (threadIdx.x < 32) {
        const unsigned long long* t64 = (const unsigned long long*)target;
        unsigned hi = (unsigned)(t64[threadIdx.x] >> 32) |
                      (unsigned)(t64[threadIdx.x + 32] >> 32);
        #pragma unroll
        for (int off = 16; off > 0; off >>= 1)
            hi |= __shfl_down_sync(0xFFFFFFFFu, hi, off);
        if (threadIdx.x == 0) s_is32 = (hi != 0);
    }
    __syncthreads();
    const int is32 = s_is32;

    int q = blockIdx.x * blockDim.x + threadIdx.x;   // quad index, 4 labels per thread
    if (q < (NB * HW) / 4) {
        uchar4 o;
        if (is32) {
            int4 v = ((const int4*)target)[q];
            o.x = (unsigned char)v.x; o.y = (unsigned char)v.y;
            o.z = (unsigned char)v.z; o.w = (unsigned char)v.w;
        } else {
            longlong2 a = ((const longlong2*)target)[2 * q];
            longlong2 b = ((const longlong2*)target)[2 * q + 1];
            o.x = (unsigned char)a.x; o.y = (unsigned char)a.y;
            o.z = (unsigned char)b.x; o.w = (unsigned char)b.y;
        }
        ((uchar4*)g_labels)[q] = o;
    }
}

// K1: one block per (b,c). Histogram of quantized errors + fused BCE partial,
// suffix scan + exact-integer Jaccard integral, and (last block) final combine.
__global__ __launch_bounds__(THREADS, 1) void lovasz_kernel(const float* __restrict__ logits,
                                                            float* __restrict__ out) {
    __shared__ unsigned int       hist[KB];      // low16 = count, high16 = positive count
    __shared__ unsigned long long sbuf[THREADS]; // scan scratch: (n<<32)|p
    __shared__ double             wsum[32][2];

    const int bc  = blockIdx.x;
    const int b   = bc >> 4;
    const int c   = bc & 15;
    const int tid = threadIdx.x;

    for (int j = tid; j < KB; j += THREADS) hist[j] = 0u;
    __syncthreads();

    const float4* lg4 = reinterpret_cast<const float4*>(logits + (size_t)bc * HW);
    const uchar4* lb4 = reinterpret_cast<const uchar4*>(g_labels + (size_t)b * HW);

    float bce_acc = 0.0f;
    const float L2E = 1.4426950408889634f;
    const float LN2 = 0.6931471805599453f;

    for (int q = tid; q < HW / 4; q += THREADS) {
        float4 z4 = lg4[q];
        uchar4 t4 = lb4[q];
        float zz[4] = { z4.x, z4.y, z4.z, z4.w };
        int   tt[4] = { t4.x, t4.y, t4.z, t4.w };
        #pragma unroll
        for (int j = 0; j < 4; j++) {
            float z   = zz[j];
            int   t   = tt[j];
            int   lbl = (t == c) ? 1 : 0;   // t==16 (ignore) never equals c
            float az  = fabsf(z);
            float u   = fast_ex2(-az * L2E);              // e^{-|z|}
            float u2  = u * u;
            float tnh = (1.0f - u2) * fast_rcp(1.0f + u2);// tanh(|z|)
            // e = 1 + s*tanh(|z|),  s = sign(z) flipped when lbl=1  (so e = 1 -/+ tanh(z))
            unsigned sx = (__float_as_uint(z) & 0x80000000u) ^ ((unsigned)lbl << 31);
            float st  = __uint_as_float(__float_as_uint(tnh) ^ sx);
            float e   = 1.0f + st;                        // in (0,2)
            int key = (int)(e * (float)(KB / 2));
            key = min(key, KB - 1);
            atomicAdd(&hist[key], 1u + ((unsigned)lbl << 16));
            // BCE: softplus(z) - lbl*z, clipped at 100, valid if t < NC
            float m   = fast_lg2(1.0f + u) * LN2;         // log1p(e^{-|z|})
            float sp  = fmaxf(z, 0.0f) + m;
            float bce = fminf(sp - (lbl ? z : 0.0f), 100.0f);
            if (t < NC) bce_acc += bce;
        }
    }
    __syncthreads();

    // Per-thread bucket totals (8 consecutive buckets each).
    unsigned int n_t = 0, p_t = 0;
    const int lo = tid * BPT;
    #pragma unroll
    for (int j = 0; j < BPT; j++) {
        unsigned v = hist[lo + j];
        n_t += v & 0xFFFFu;
        p_t += v >> 16;
    }
    sbuf[tid] = ((unsigned long long)n_t << 32) | (unsigned long long)p_t;
    __syncthreads();
    // Inclusive SUFFIX scan (descending-error order).
    for (int d = 1; d < THREADS; d <<= 1) {
        unsigned long long v = (tid + d < THREADS) ? sbuf[tid + d] : 0ULL;
        __syncthreads();
        sbuf[tid] += v;
        __syncthreads();
    }
    const unsigned long long tot = sbuf[0];
    const long long P = (long long)(tot & 0xFFFFFFFFULL);
    unsigned long long inc = sbuf[tid];
    long long i0 = (long long)(inc >> 32) - (long long)n_t;
    long long p0 = (long long)(inc & 0xFFFFFFFFULL) - (long long)p_t;

    // Walk buckets high->low; exact integer Jaccard deltas.
    double contrib = 0.0;
    const double de = 2.0 / (double)KB;
    for (int j = BPT - 1; j >= 0; j--) {
        unsigned v = hist[lo + j];
        long long n = (long long)(v & 0xFFFFu);
        long long p = (long long)(v >> 16);
        if (n > 0) {
            long long i1 = i0 + n, p1 = p0 + p;
            double dJ;
            if (P > 0) {
                long long A0 = P - p0, B0 = P + i0 - p0;
                long long A1 = P - p1, B1 = P + i1 - p1;
                dJ = (double)(A0 * B1 - A1 * B0) / ((double)B0 * (double)B1);
            } else {
                dJ = (i0 == 0) ? 1.0 : 0.0;
            }
            contrib += ((double)(lo + j) + 0.5) * de * dJ;
            i0 = i1; p0 = p1;
        }
    }

    // Deterministic block reduction.
    double bced = (double)bce_acc;
    const unsigned mask = 0xFFFFFFFFu;
    #pragma unroll
    for (int off = 16; off > 0; off >>= 1) {
        contrib += __shfl_down_sync(mask, contrib, off);
        bced    += __shfl_down_sync(mask, bced, off);
    }
    const int wid = tid >> 5, lane = tid & 31;
    if (lane == 0) { wsum[wid][0] = contrib; wsum[wid][1] = bced; }
    __syncthreads();
    if (wid == 0) {
        double cv = wsum[lane][0];
        double bv = wsum[lane][1];
        #pragma unroll
        for (int off = 16; off > 0; off >>= 1) {
            cv += __shfl_down_sync(mask, cv, off);
            bv += __shfl_down_sync(mask, bv, off);
        }
        if (lane == 0) { g_part[bc * 2 + 0] = cv; g_part[bc * 2 + 1] = bv; }
    }

    // Last-arriving block performs the deterministic final combine.
    __shared__ unsigned s_rank;
    __threadfence();
    __syncthreads();
    if (tid == 0) s_rank = atomicAdd(&g_arrive, 1u);
    __syncthreads();
    if (s_rank == NBC - 1) {
        __threadfence();  // acquire all g_part writes
        __shared__ double fin[NBC][2];
        if (tid < NBC) {
            fin[tid][0] = g_part[tid * 2];
            fin[tid][1] = g_part[tid * 2 + 1];
        }
        __syncthreads();
        // Fixed-order pairwise tree (deterministic regardless of which block runs it).
        for (int stride = NBC / 2; stride > 0; stride >>= 1) {
            if (tid < stride) {
                fin[tid][0] += fin[tid + stride][0];
                fin[tid][1] += fin[tid + stride][1];
            }
            __syncthreads();
        }
        if (tid == 0) {
            out[0] = (float)(fin[0][0] * (1.0 / 128.0) + fin[0][1] * (1.0 / 33554432.0));
            g_arrive = 0;  // reset for next graph replay
        }
    }
}

extern "C" void kernel_launch(void* const* d_in, const int* in_sizes, int n_in,
                              void* d_out, int out_size) {
    const float* logits;
    const void*  target;
    if (in_sizes[0] == NB * NC * HW) {
        logits = (const float*)d_in[0];
        target = d_in[1];
    } else {
        logits = (const float*)d_in[1];
        target = d_in[0];
    }
    prep_kernel<<<(NB * HW / 4 + THREADS - 1) / THREADS, THREADS>>>(target);
    lovasz_kernel<<<NBC, THREADS>>>(logits, (float*)d_out);
}

// round 5
// speedup vs baseline: 1.6301x; 1.3584x over previous
#include <cuda_runtime.h>
#include <cstdint>

#define HW      262144
#define NB      8
#define NC      16
#define NBC     (NB * NC)          // 128 class-planes
#define KB      8192               // histogram buckets over error in (0,2)
#define THREADS 1024
#define BPT     (KB / THREADS)     // 8 buckets per thread

// Scratch (no allocations allowed)
__device__ unsigned char g_labels[NB * HW];
__device__ double        g_part[NBC * 2];   // [bc*2]=lovasz, [bc*2+1]=bce
__device__ unsigned int  g_arrive;          // zero-initialized; reset by combiner each call

__device__ __forceinline__ float fast_tanh(float x) { float y; asm("tanh.approx.f32 %0, %1;" : "=f"(y) : "f"(x)); return y; }
__device__ __forceinline__ float fast_lg2(float x)  { float y; asm("lg2.approx.f32 %0, %1;"  : "=f"(y) : "f"(x)); return y; }
__device__ __forceinline__ float fast_rcp(float x)  { float y; asm("rcp.approx.f32 %0, %1;"  : "=f"(y) : "f"(x)); return y; }

// K0: target (int32 or int64) -> uint8. Dtype detected per-block (uniform branch).
__global__ __launch_bounds__(THREADS) void prep_kernel(const void* __restrict__ target) {
    __shared__ int s_is32;
    if (threadIdx.x < 32) {
        const unsigned long long* t64 = (const unsigned long long*)target;
        unsigned hi = (unsigned)(t64[threadIdx.x] >> 32) |
                      (unsigned)(t64[threadIdx.x + 32] >> 32);
        #pragma unroll
        for (int off = 16; off > 0; off >>= 1)
            hi |= __shfl_down_sync(0xFFFFFFFFu, hi, off);
        if (threadIdx.x == 0) s_is32 = (hi != 0);
    }
    __syncthreads();
    const int is32 = s_is32;

    int q = blockIdx.x * blockDim.x + threadIdx.x;   // quad index
    if (q < (NB * HW) / 4) {
        uchar4 o;
        if (is32) {
            int4 v = ((const int4*)target)[q];
            o.x = (unsigned char)v.x; o.y = (unsigned char)v.y;
            o.z = (unsigned char)v.z; o.w = (unsigned char)v.w;
        } else {
            longlong2 a = ((const longlong2*)target)[2 * q];
            longlong2 b = ((const longlong2*)target)[2 * q + 1];
            o.x = (unsigned char)a.x; o.y = (unsigned char)a.y;
            o.z = (unsigned char)b.x; o.w = (unsigned char)b.y;
        }
        ((uchar4*)g_labels)[q] = o;
    }
}

// K1: one block per (b,c). Minimal hot loop: tanh -> bucket key -> one smem atomic.
// Histogram packs n(16b) | pos(8b) | ign(8b). BCE is evaluated per-BUCKET in the
// scan phase via bce(e) = log1p(sqrt(e/(2-e))) (label-independent identity).
__global__ __launch_bounds__(THREADS, 1) void lovasz_kernel(const float* __restrict__ logits,
                                                            float* __restrict__ out) {
    __shared__ unsigned int       hist[KB];
    __shared__ unsigned long long sbuf[THREADS]; // scan scratch: (n<<32)|p
    __shared__ double             wsum[32][2];

    const int bc  = blockIdx.x;
    const int b   = bc >> 4;
    const int c   = bc & 15;
    const int tid = threadIdx.x;

    for (int j = tid; j < KB; j += THREADS) hist[j] = 0u;
    __syncthreads();

    const float4* lg4 = reinterpret_cast<const float4*>(logits + (size_t)bc * HW);
    const uchar4* lb4 = reinterpret_cast<const uchar4*>(g_labels + (size_t)b * HW);

    #pragma unroll 2
    for (int q = tid; q < HW / 4; q += THREADS) {
        float4 z4 = lg4[q];
        uchar4 t4 = lb4[q];
        float zz[4] = { z4.x, z4.y, z4.z, z4.w };
        int   tt[4] = { t4.x, t4.y, t4.z, t4.w };
        #pragma unroll
        for (int j = 0; j < 4; j++) {
            float z   = zz[j];
            int   t   = tt[j];
            unsigned lbl = (t == c) ? 1u : 0u;            // t==16 (ignore) never equals c
            float x   = fast_tanh(z);
            // e = 1 - x when lbl, 1 + x otherwise: flip sign bit by lbl
            float st  = __uint_as_float(__float_as_uint(x) ^ (lbl << 31));
            float e   = 1.0f + st;                        // in [0,2] (approx may touch ends)
            int key   = (int)(e * (float)(KB / 2));
            key = max(min(key, KB - 1), 0);
            unsigned inc = 1u + (lbl << 16) + ((t == NC) ? 0x1000000u : 0u);
            atomicAdd(&hist[key], inc);
        }
    }
    __syncthreads();

    // Per-thread bucket totals + per-bucket BCE (8 consecutive buckets each).
    unsigned int n_t = 0, p_t = 0;
    double bced = 0.0;
    const int lo = tid * BPT;
    const float LN2 = 0.6931471805599453f;
    #pragma unroll
    for (int j = 0; j < BPT; j++) {
        unsigned v = hist[lo + j];
        unsigned n = v & 0xFFFFu;
        unsigned p = (v >> 16) & 0xFFu;
        unsigned g = v >> 24;
        n_t += n;
        p_t += p;
        // bce(e_mid) = log1p(sqrt(e/(2-e))), valid count = n - ign
        float em = ((float)(lo + j) + 0.5f) * (2.0f / (float)KB);
        float s  = sqrtf(em * fast_rcp(2.0f - em));
        float gb = fast_lg2(1.0f + s) * LN2;
        bced += (double)(n - g) * (double)gb;
    }
    sbuf[tid] = ((unsigned long long)n_t << 32) | (unsigned long long)p_t;
    __syncthreads();
    // Inclusive SUFFIX scan (descending-error order).
    for (int d = 1; d < THREADS; d <<= 1) {
        unsigned long long v = (tid + d < THREADS) ? sbuf[tid + d] : 0ULL;
        __syncthreads();
        sbuf[tid] += v;
        __syncthreads();
    }
    const unsigned long long tot = sbuf[0];
    const long long P = (long long)(tot & 0xFFFFFFFFULL);
    unsigned long long inc2 = sbuf[tid];
    long long i0 = (long long)(inc2 >> 32) - (long long)n_t;
    long long p0 = (long long)(inc2 & 0xFFFFFFFFULL) - (long long)p_t;

    // Walk buckets high->low; exact integer Jaccard deltas.
    double contrib = 0.0;
    const double de = 2.0 / (double)KB;
    for (int j = BPT - 1; j >= 0; j--) {
        unsigned v = hist[lo + j];
        long long n = (long long)(v & 0xFFFFu);
        long long p = (long long)((v >> 16) & 0xFFu);
        if (n > 0) {
            long long i1 = i0 + n, p1 = p0 + p;
            double dJ;
            if (P > 0) {
                long long A0 = P - p0, B0 = P + i0 - p0;
                long long A1 = P - p1, B1 = P + i1 - p1;
                dJ = (double)(A0 * B1 - A1 * B0) / ((double)B0 * (double)B1);
            } else {
                dJ = (i0 == 0) ? 1.0 : 0.0;
            }
            contrib += ((double)(lo + j) + 0.5) * de * dJ;
            i0 = i1; p0 = p1;
        }
    }

    // Deterministic block reduction.
    const unsigned mask = 0xFFFFFFFFu;
    #pragma unroll
    for (int off = 16; off > 0; off >>= 1) {
        contrib += __shfl_down_sync(mask, contrib, off);
        bced    += __shfl_down_sync(mask, bced, off);
    }
    const int wid = tid >> 5, lane = tid & 31;
    if (lane == 0) { wsum[wid][0] = contrib; wsum[wid][1] = bced; }
    __syncthreads();
    if (wid == 0) {
        double cv = wsum[lane][0];
        double bv = wsum[lane][1];
        #pragma unroll
        for (int off = 16; off > 0; off >>= 1) {
            cv += __shfl_down_sync(mask, cv, off);
            bv += __shfl_down_sync(mask, bv, off);
        }
        if (lane == 0) { g_part[bc * 2 + 0] = cv; g_part[bc * 2 + 1] = bv; }
    }

    // Last-arriving block performs the deterministic final combine.
    __shared__ unsigned s_rank;
    __threadfence();
    __syncthreads();
    if (tid == 0) s_rank = atomicAdd(&g_arrive, 1u);
    __syncthreads();
    if (s_rank == NBC - 1) {
        __threadfence();
        __shared__ double fin[NBC][2];
        if (tid < NBC) {
            fin[tid][0] = g_part[tid * 2];
            fin[tid][1] = g_part[tid * 2 + 1];
        }
        __syncthreads();
        for (int stride = NBC / 2; stride > 0; stride >>= 1) {
            if (tid < stride) {
                fin[tid][0] += fin[tid + stride][0];
                fin[tid][1] += fin[tid + stride][1];
            }
            __syncthreads();
        }
        if (tid == 0) {
            out[0] = (float)(fin[0][0] * (1.0 / 128.0) + fin[0][1] * (1.0 / 33554432.0));
            g_arrive = 0;
        }
    }
}

extern "C" void kernel_launch(void* const* d_in, const int* in_sizes, int n_in,
                              void* d_out, int out_size) {
    const float* logits;
    const void*  target;
    if (in_sizes[0] == NB * NC * HW) {
        logits = (const float*)d_in[0];
        target = d_in[1];
    } else {
        logits = (const float*)d_in[1];
        target = d_in[0];
    }
    prep_kernel<<<(NB * HW / 4 + THREADS - 1) / THREADS, THREADS>>>(target);
    lovasz_kernel<<<NBC, THREADS>>>(logits, (float*)d_out);
}

// round 6
// speedup vs baseline: 1.8199x; 1.1165x over previous
#include <cuda_runtime.h>
#include <cstdint>

#define HW      262144
#define NB      8
#define NC      16
#define NBC     (NB * NC)          // 128 class-planes
#define KB      8192               // histogram buckets over x=tanh(z) in (-1,1)
#define THREADS 1024
#define BPT     (KB / THREADS)     // 8 e-buckets per thread
#define DYN_SMEM (2 * KB * 4 + THREADS * 8)   // dual hist + scan buffer

// Scratch (no allocations allowed)
__device__ unsigned char g_labels[NB * HW];
__device__ double        g_part[NBC * 2];   // [bc*2]=lovasz, [bc*2+1]=bce
__device__ unsigned int  g_arrive;          // zero-init; reset by combiner each call

__device__ __forceinline__ float fast_tanh(float x) { float y; asm("tanh.approx.f32 %0, %1;" : "=f"(y) : "f"(x)); return y; }
__device__ __forceinline__ float fast_lg2(float x)  { float y; asm("lg2.approx.f32 %0, %1;"  : "=f"(y) : "f"(x)); return y; }
__device__ __forceinline__ float fast_rcp(float x)  { float y; asm("rcp.approx.f32 %0, %1;"  : "=f"(y) : "f"(x)); return y; }

// K0: target (int32 or int64) -> uint8. Dtype detected per-block (uniform branch).
__global__ __launch_bounds__(THREADS) void prep_kernel(const void* __restrict__ target) {
    __shared__ int s_is32;
    if (threadIdx.x < 32) {
        const unsigned long long* t64 = (const unsigned long long*)target;
        unsigned hi = (unsigned)(t64[threadIdx.x] >> 32) |
                      (unsigned)(t64[threadIdx.x + 32] >> 32);
        #pragma unroll
        for (int off = 16; off > 0; off >>= 1)
            hi |= __shfl_down_sync(0xFFFFFFFFu, hi, off);
        if (threadIdx.x == 0) s_is32 = (hi != 0);
    }
    __syncthreads();
    const int is32 = s_is32;

    int q = blockIdx.x * blockDim.x + threadIdx.x;   // quad index
    if (q < (NB * HW) / 4) {
        uchar4 o;
        if (is32) {
            int4 v = ((const int4*)target)[q];
            o.x = (unsigned char)v.x; o.y = (unsigned char)v.y;
            o.z = (unsigned char)v.z; o.w = (unsigned char)v.w;
        } else {
            longlong2 a = ((const longlong2*)target)[2 * q];
            longlong2 b = ((const longlong2*)target)[2 * q + 1];
            o.x = (unsigned char)a.x; o.y = (unsigned char)a.y;
            o.z = (unsigned char)b.x; o.w = (unsigned char)b.y;
        }
        ((uchar4*)g_labels)[q] = o;
    }
}

// K1: one block per (b,c). Hot loop: tanh -> x-bucket key -> one smem atomic
// into a warp-parity-private histogram copy. hist packs n(16b)|pos(8b)|ign(8b).
// Scan phase converts x-buckets to descending-e order (neg: e=1+x at bucket j;
// pos: e=1-x at mirrored bucket KB-1-j), evaluates per-bucket BCE via
// bce(e)=log1p(sqrt(e/(2-e))), suffix-scans, and integrates exact Jaccard deltas.
__global__ __launch_bounds__(THREADS, 1) void lovasz_kernel(const float* __restrict__ logits,
                                                            float* __restrict__ out) {
    extern __shared__ unsigned int dyn[];
    unsigned int*       hist = dyn;                                  // 2*KB entries
    unsigned long long* sbuf = (unsigned long long*)(dyn + 2 * KB);  // THREADS entries
    __shared__ double wsum[32][2];
    __shared__ double fin[NBC][2];
    __shared__ unsigned s_rank;

    const int bc  = blockIdx.x;
    const int b   = bc >> 4;
    const int c   = bc & 15;
    const int tid = threadIdx.x;

    for (int j = tid; j < 2 * KB; j += THREADS) hist[j] = 0u;
    __syncthreads();

    const float4* lg4 = reinterpret_cast<const float4*>(logits + (size_t)bc * HW);
    const uchar4* lb4 = reinterpret_cast<const uchar4*>(g_labels + (size_t)b * HW);
    unsigned int* myhist = hist + (((tid >> 5) & 1) << 13);  // warp-parity copy

    #pragma unroll 4
    for (int q = tid; q < HW / 4; q += THREADS) {
        float4 z4 = lg4[q];
        uchar4 t4 = lb4[q];
        float zz[4] = { z4.x, z4.y, z4.z, z4.w };
        int   tt[4] = { t4.x, t4.y, t4.z, t4.w };
        #pragma unroll
        for (int j = 0; j < 4; j++) {
            float x = fast_tanh(zz[j]);
            int key = (int)fmaf(x, (float)(KB / 2), (float)(KB / 2));
            key = min(key, KB - 1);
            int t = tt[j];
            unsigned inc = 1u + ((t == c) ? 0x10000u : 0u) + ((unsigned)(t >> 4) << 24);
            atomicAdd(myhist + key, inc);
        }
    }
    __syncthreads();

    // Cold phase: per-thread e-bucket counts (8 consecutive e-buckets each),
    // merging dual copies + mirrored positive mapping, fused per-bucket BCE.
    unsigned ne[BPT], pe[BPT];
    unsigned n_t = 0, p_t = 0;
    double bced = 0.0;
    const int lo = tid * BPT;
    const float LN2 = 0.6931471805599453f;
    #pragma unroll
    for (int j = 0; j < BPT; j++) {
        const int eb = lo + j;
        const int mb = KB - 1 - eb;
        unsigned va = hist[eb] + hist[eb + KB];   // packed add: fields can't overflow
        unsigned vb = hist[mb] + hist[mb + KB];
        unsigned nA = va & 0xFFFFu;
        unsigned pA = (va >> 16) & 0xFFu;
        unsigned iA = va >> 24;
        unsigned pB = (vb >> 16) & 0xFFu;
        ne[j] = nA - pA + pB;                     // total count at error-bucket eb
        pe[j] = pB;                               // positives at error-bucket eb
        n_t += ne[j]; p_t += pe[j];
        // BCE: valid count (exclude ignored negatives; positives never ignored)
        float em = ((float)eb + 0.5f) * (2.0f / (float)KB);
        float s  = sqrtf(em * fast_rcp(2.0f - em));
        float gb = fast_lg2(1.0f + s) * LN2;
        bced += (double)(nA - pA - iA + pB) * (double)gb;
    }
    sbuf[tid] = ((unsigned long long)n_t << 32) | (unsigned long long)p_t;
    __syncthreads();
    // Inclusive SUFFIX scan (descending-error order).
    for (int d = 1; d < THREADS; d <<= 1) {
        unsigned long long v = (tid + d < THREADS) ? sbuf[tid + d] : 0ULL;
        __syncthreads();
        sbuf[tid] += v;
        __syncthreads();
    }
    const unsigned long long tot = sbuf[0];
    const long long P = (long long)(tot & 0xFFFFFFFFULL);
    unsigned long long inc2 = sbuf[tid];
    long long i0 = (long long)(inc2 >> 32) - (long long)n_t;
    long long p0 = (long long)(inc2 & 0xFFFFFFFFULL) - (long long)p_t;

    // Walk e-buckets high->low; exact integer Jaccard deltas.
    double contrib = 0.0;
    const double de = 2.0 / (double)KB;
    #pragma unroll
    for (int j = BPT - 1; j >= 0; j--) {
        long long n = (long long)ne[j];
        long long p = (long long)pe[j];
        if (n > 0) {
            long long i1 = i0 + n, p1 = p0 + p;
            double dJ;
            if (P > 0) {
                long long A0 = P - p0, B0 = P + i0 - p0;
                long long A1 = P - p1, B1 = P + i1 - p1;
                dJ = (double)(A0 * B1 - A1 * B0) / ((double)B0 * (double)B1);
            } else {
                dJ = (i0 == 0) ? 1.0 : 0.0;
            }
            contrib += ((double)(lo + j) + 0.5) * de * dJ;
            i0 = i1; p0 = p1;
        }
    }

    // Deterministic block reduction.
    const unsigned mask = 0xFFFFFFFFu;
    #pragma unroll
    for (int off = 16; off > 0; off >>= 1) {
        contrib += __shfl_down_sync(mask, contrib, off);
        bced    += __shfl_down_sync(mask, bced, off);
    }
    const int wid = tid >> 5, lane = tid & 31;
    if (lane == 0) { wsum[wid][0] = contrib; wsum[wid][1] = bced; }
    __syncthreads();
    if (wid == 0) {
        double cv = wsum[lane][0];
        double bv = wsum[lane][1];
        #pragma unroll
        for (int off = 16; off > 0; off >>= 1) {
            cv += __shfl_down_sync(mask, cv, off);
            bv += __shfl_down_sync(mask, bv, off);
        }
        if (lane == 0) { g_part[bc * 2 + 0] = cv; g_part[bc * 2 + 1] = bv; }
    }

    // Last-arriving block performs the deterministic final combine.
    __threadfence();
    __syncthreads();
    if (tid == 0) s_rank = atomicAdd(&g_arrive, 1u);
    __syncthreads();
    if (s_rank == NBC - 1) {
        __threadfence();
        if (tid < NBC) {
            fin[tid][0] = g_part[tid * 2];
            fin[tid][1] = g_part[tid * 2 + 1];
        }
        __syncthreads();
        for (int stride = NBC / 2; stride > 0; stride >>= 1) {
            if (tid < stride) {
                fin[tid][0] += fin[tid + stride][0];
                fin[tid][1] += fin[tid + stride][1];
            }
            __syncthreads();
        }
        if (tid == 0) {
            out[0] = (float)(fin[0][0] * (1.0 / 128.0) + fin[0][1] * (1.0 / 33554432.0));
            g_arrive = 0;
        }
    }
}

extern "C" void kernel_launch(void* const* d_in, const int* in_sizes, int n_in,
                              void* d_out, int out_size) {
    const float* logits;
    const void*  target;
    if (in_sizes[0] == NB * NC * HW) {
        logits = (const float*)d_in[0];
        target = d_in[1];
    } else {
        logits = (const float*)d_in[1];
        target = d_in[0];
    }
    cudaFuncSetAttribute(lovasz_kernel, cudaFuncAttributeMaxDynamicSharedMemorySize, DYN_SMEM);
    prep_kernel<<<(NB * HW / 4 + THREADS - 1) / THREADS, THREADS>>>(target);
    lovasz_kernel<<<NBC, THREADS, DYN_SMEM>>>(logits, (float*)d_out);
}